// round 1
// baseline (speedup 1.0000x reference)
#include <cuda_runtime.h>
#include <cstddef>

#define NN   8192
#define HID  192
#define INF  256
#define MAXN 128

// ---- device scratch (no allocations allowed) ----
__device__ float g_support[NN * HID];
__device__ float g_xbuf[NN * HID];
__device__ float g_featbuf[NN * HID];
__device__ int   g_nidx[NN * MAXN];
__device__ float g_nval[NN * MAXN];
__device__ int   g_ncnt[NN];

// ---- sparse adjacency extraction: warp per row, ordered compaction ----
__global__ __launch_bounds__(256) void build_csr(const float* __restrict__ adj,
                                                 int* __restrict__ nidx,
                                                 float* __restrict__ nval,
                                                 int* __restrict__ ncnt)
{
    int warp = (blockIdx.x * blockDim.x + threadIdx.x) >> 5;
    int lane = threadIdx.x & 31;
    if (warp >= NN) return;
    const float4* row = reinterpret_cast<const float4*>(adj + (size_t)warp * NN);
    int* my_idx = nidx + (size_t)warp * MAXN;
    float* my_val = nval + (size_t)warp * MAXN;
    int count = 0;
    for (int it = 0; it < NN / 128; it++) {
        float4 v = row[it * 32 + lane];
        int c0 = it * 128 + lane * 4;
        int my = (v.x != 0.f) + (v.y != 0.f) + (v.z != 0.f) + (v.w != 0.f);
        int inc = my;
        #pragma unroll
        for (int d = 1; d < 32; d <<= 1) {
            int t = __shfl_up_sync(0xffffffffu, inc, d);
            if (lane >= d) inc += t;
        }
        int total = __shfl_sync(0xffffffffu, inc, 31);
        int pos = count + inc - my;
        if (v.x != 0.f) { if (pos < MAXN) { my_idx[pos] = c0;     my_val[pos] = v.x; } pos++; }
        if (v.y != 0.f) { if (pos < MAXN) { my_idx[pos] = c0 + 1; my_val[pos] = v.y; } pos++; }
        if (v.z != 0.f) { if (pos < MAXN) { my_idx[pos] = c0 + 2; my_val[pos] = v.z; } pos++; }
        if (v.w != 0.f) { if (pos < MAXN) { my_idx[pos] = c0 + 3; my_val[pos] = v.w; } pos++; }
        count += total;
    }
    if (lane == 0) ncnt[warp] = count > MAXN ? MAXN : count;
}

// ---- SGEMM: S[M,192] = X[M,K] @ W[K,192].  BM=32, BK=32, BN=192, 256 thr ----
__global__ __launch_bounds__(256) void gemm_kernel(const float* __restrict__ X,
                                                   const float* __restrict__ W,
                                                   float* __restrict__ S, int K)
{
    __shared__ float As[32][36];     // padded, float4-aligned columns
    __shared__ float Bs[32][192];
    int tid = threadIdx.x;
    int m0 = blockIdx.x * 32;
    int trow = tid >> 5;             // 0..7  -> rows trow*4 + i
    int tcol = tid & 31;             // 0..31 -> cols tcol + 32*j
    float acc[4][6];
    #pragma unroll
    for (int i = 0; i < 4; i++)
        #pragma unroll
        for (int j = 0; j < 6; j++) acc[i][j] = 0.f;

    int arow = tid >> 3;             // 0..31
    int akg  = (tid & 7) * 4;        // 0,4,...,28

    for (int k0 = 0; k0 < K; k0 += 32) {
        float4 av = *reinterpret_cast<const float4*>(X + (size_t)(m0 + arow) * K + k0 + akg);
        *reinterpret_cast<float4*>(&As[arow][akg]) = av;
        #pragma unroll
        for (int s = 0; s < 6; s++) {
            int slot = tid + 256 * s;        // 0..1535 float4 slots
            int bk = slot / 48;
            int bc = (slot % 48) * 4;
            float4 bv = *reinterpret_cast<const float4*>(W + (size_t)(k0 + bk) * HID + bc);
            *reinterpret_cast<float4*>(&Bs[bk][bc]) = bv;
        }
        __syncthreads();
        #pragma unroll
        for (int k = 0; k < 32; k++) {
            float a[4], b[6];
            #pragma unroll
            for (int i = 0; i < 4; i++) a[i] = As[trow * 4 + i][k];
            #pragma unroll
            for (int j = 0; j < 6; j++) b[j] = Bs[k][tcol + 32 * j];
            #pragma unroll
            for (int i = 0; i < 4; i++)
                #pragma unroll
                for (int j = 0; j < 6; j++) acc[i][j] = fmaf(a[i], b[j], acc[i][j]);
        }
        __syncthreads();
    }
    #pragma unroll
    for (int i = 0; i < 4; i++) {
        size_t r = m0 + trow * 4 + i;
        #pragma unroll
        for (int j = 0; j < 6; j++)
            S[r * HID + tcol + 32 * j] = acc[i][j];
    }
}

// ---- tiny GEMM for W_out (192x3) ----
__global__ __launch_bounds__(256) void gemm3_kernel(const float* __restrict__ X,
                                                    const float* __restrict__ W,
                                                    float* __restrict__ S)
{
    int r = blockIdx.x * blockDim.x + threadIdx.x;
    if (r >= NN) return;
    const float* x = X + (size_t)r * HID;
    float a0 = 0.f, a1 = 0.f, a2 = 0.f;
    #pragma unroll 4
    for (int k = 0; k < HID; k++) {
        float xv = x[k];
        a0 = fmaf(xv, W[k * 3 + 0], a0);
        a1 = fmaf(xv, W[k * 3 + 1], a1);
        a2 = fmaf(xv, W[k * 3 + 2], a2);
    }
    S[r * 3 + 0] = a0; S[r * 3 + 1] = a1; S[r * 3 + 2] = a2;
}

// ---- fused aggregation + bias + relu + residual.  warp per node ----
__global__ __launch_bounds__(256) void agg_kernel(const float* __restrict__ S,
                                                  const float* __restrict__ bias,
                                                  const float* __restrict__ res, int res_stride,
                                                  float* __restrict__ out,
                                                  float* __restrict__ out2,
                                                  const int* __restrict__ nidx,
                                                  const float* __restrict__ nval,
                                                  const int* __restrict__ ncnt,
                                                  int n_out, int side, int do_relu)
{
    int warp = (blockIdx.x * blockDim.x + threadIdx.x) >> 5;
    int lane = threadIdx.x & 31;
    if (warp >= NN) return;
    int cnt = ncnt[warp];
    const int* ni = nidx + (size_t)warp * MAXN;
    const float* nv = nval + (size_t)warp * MAXN;
    float acc0 = 0.f, acc1 = 0.f;   // side <= 64 always
    if (side > 32) {
        for (int i = 0; i < cnt; i++) {
            const float* sr = S + (size_t)ni[i] * n_out;
            float v = nv[i];
            acc0 = fmaf(v, sr[lane], acc0);
            acc1 = fmaf(v, sr[lane + 32], acc1);
        }
    } else {
        for (int i = 0; i < cnt; i++) {
            if (lane < side) acc0 = fmaf(nv[i], S[(size_t)ni[i] * n_out + lane], acc0);
        }
    }
    int nj = (n_out + 31) >> 5;
    for (int j = 0; j < nj; j++) {
        int c = 32 * j + lane;
        if (c < n_out) {
            float t = (c < side) ? (j == 0 ? acc0 : acc1)
                                 : S[(size_t)warp * n_out + c];
            t += bias[c];
            if (do_relu) t = fmaxf(t, 0.f);
            if (res) t = (res[(size_t)warp * res_stride + c] + t) * 0.5f;
            out[(size_t)warp * n_out + c] = t;
            if (out2) out2[(size_t)warp * n_out + c] = t;
        }
    }
}

extern "C" void kernel_launch(void* const* d_in, const int* in_sizes, int n_in,
                              void* d_out, int out_size)
{
    const float* features = (const float*)d_in[0];   // [8192,256]
    const float* adj      = (const float*)d_in[1];   // [8192,8192]
    const float* W1       = (const float*)d_in[2];   // [256,192]
    const float* b1       = (const float*)d_in[3];   // [192]
    const float* W_mid    = (const float*)d_in[4];   // [12,192,192]
    const float* b_mid    = (const float*)d_in[5];   // [12,192]
    const float* W_out    = (const float*)d_in[6];   // [192,3]
    const float* b_out    = (const float*)d_in[7];   // [3]
    float* out = (float*)d_out;
    float* coords   = out;            // [8192*3]
    float* feat_out = out + NN * 3;   // [8192*192]

    float *sup, *xb, *fb, *nval;
    int *nidx, *ncnt;
    cudaGetSymbolAddress((void**)&sup,  g_support);
    cudaGetSymbolAddress((void**)&xb,   g_xbuf);
    cudaGetSymbolAddress((void**)&fb,   g_featbuf);
    cudaGetSymbolAddress((void**)&nidx, g_nidx);
    cudaGetSymbolAddress((void**)&nval, g_nval);
    cudaGetSymbolAddress((void**)&ncnt, g_ncnt);

    build_csr<<<NN / 8, 256>>>(adj, nidx, nval, ncnt);

    // gc1: x = relu(zngcn(features, W1, b1))
    gemm_kernel<<<NN / 32, 256>>>(features, W1, sup, INF);
    agg_kernel<<<NN / 8, 256>>>(sup, b1, nullptr, 0, xb, nullptr,
                                nidx, nval, ncnt, HID, 64, 1);
    // gc2 + residual against features[:, :192] (stride 256)
    gemm_kernel<<<NN / 32, 256>>>(xb, W_mid + 0, sup, HID);
    agg_kernel<<<NN / 8, 256>>>(sup, b_mid + 0, features, INF, fb, nullptr,
                                nidx, nval, ncnt, HID, 64, 1);

    const int pair_idx[5] = {1, 3, 5, 7, 9};
    for (int p = 0; p < 5; p++) {
        int i = pair_idx[p];
        gemm_kernel<<<NN / 32, 256>>>(fb, W_mid + (size_t)i * HID * HID, sup, HID);
        agg_kernel<<<NN / 8, 256>>>(sup, b_mid + (size_t)i * HID, nullptr, 0, xb, nullptr,
                                    nidx, nval, ncnt, HID, 64, 1);
        gemm_kernel<<<NN / 32, 256>>>(xb, W_mid + (size_t)(i + 1) * HID * HID, sup, HID);
        agg_kernel<<<NN / 8, 256>>>(sup, b_mid + (size_t)(i + 1) * HID, fb, HID, fb, nullptr,
                                    nidx, nval, ncnt, HID, 64, 1);
    }

    // gc13 (+ residual); also writes feat to output region
    gemm_kernel<<<NN / 32, 256>>>(fb, W_mid + (size_t)11 * HID * HID, sup, HID);
    agg_kernel<<<NN / 8, 256>>>(sup, b_mid + (size_t)11 * HID, fb, HID, fb, feat_out,
                                nidx, nval, ncnt, HID, 64, 1);

    // gc14: coords = zngcn(feat, W_out, b_out), side_len=2, no relu
    gemm3_kernel<<<NN / 256, 256>>>(fb, W_out, sup);
    agg_kernel<<<NN / 8, 256>>>(sup, b_out, nullptr, 0, coords, nullptr,
                                nidx, nval, ncnt, 3, 2, 0);
}

// round 3
// speedup vs baseline: 1.3494x; 1.3494x over previous
#include <cuda_runtime.h>
#include <cuda_bf16.h>
#include <cstdint>
#include <cstddef>

#define NN   8192
#define HID  192
#define INF  256
#define MAXN 128

// ---------------- device scratch ----------------
__device__ float g_support[NN * HID];
__device__ float g_featbuf[NN * HID];
__device__ float g_xbuf[NN * HID];
__device__ __nv_bfloat16 g_xhi[NN * INF];
__device__ __nv_bfloat16 g_xlo[NN * INF];
// transposed weights: W1t [192][256] at 0, W_mid[i]t [192][192] after
#define WT_TOTAL (192*256 + 12*192*192)
__device__ __nv_bfloat16 g_wthi[WT_TOTAL];
__device__ __nv_bfloat16 g_wtlo[WT_TOTAL];
__device__ int   g_nidx[NN * MAXN];
__device__ float g_nval[NN * MAXN];
__device__ int   g_ncnt[NN];

// ---------------- PTX helpers (compute_103-safe: no tcgen05) ----------------
__device__ __forceinline__ uint32_t smem_u32(const void* p) {
    uint32_t a;
    asm("{ .reg .u64 t; cvta.to.shared.u64 t, %1; cvt.u32.u64 %0, t; }" : "=r"(a) : "l"(p));
    return a;
}
__device__ __forceinline__ void cp16(uint32_t d, const void* s) {
    asm volatile("cp.async.cg.shared.global [%0], [%1], 16;" :: "r"(d), "l"(s));
}
__device__ __forceinline__ void cp_commit() {
    asm volatile("cp.async.commit_group;" ::: "memory");
}
template <int N> __device__ __forceinline__ void cp_wait() {
    asm volatile("cp.async.wait_group %0;" :: "n"(N) : "memory");
}
__device__ __forceinline__ void ldmx4(uint32_t* r, uint32_t a) {
    asm volatile("ldmatrix.sync.aligned.m8n8.x4.shared.b16 {%0,%1,%2,%3}, [%4];"
        : "=r"(r[0]), "=r"(r[1]), "=r"(r[2]), "=r"(r[3]) : "r"(a));
}
__device__ __forceinline__ void mma16816(float* d, const uint32_t* a, const uint32_t* b) {
    asm volatile("mma.sync.aligned.m16n8k16.row.col.f32.bf16.bf16.f32 "
        "{%0,%1,%2,%3}, {%4,%5,%6,%7}, {%8,%9}, {%0,%1,%2,%3};"
        : "+f"(d[0]), "+f"(d[1]), "+f"(d[2]), "+f"(d[3])
        : "r"(a[0]), "r"(a[1]), "r"(a[2]), "r"(a[3]), "r"(b[0]), "r"(b[1]));
}

// ---------------- CSR extraction ----------------
__global__ __launch_bounds__(256) void build_csr(const float* __restrict__ adj,
                                                 int* __restrict__ nidx,
                                                 float* __restrict__ nval,
                                                 int* __restrict__ ncnt)
{
    int warp = (blockIdx.x * blockDim.x + threadIdx.x) >> 5;
    int lane = threadIdx.x & 31;
    if (warp >= NN) return;
    const float4* row = reinterpret_cast<const float4*>(adj + (size_t)warp * NN);
    int* my_idx = nidx + (size_t)warp * MAXN;
    float* my_val = nval + (size_t)warp * MAXN;
    int count = 0;
    for (int it = 0; it < NN / 128; it++) {
        float4 v = row[it * 32 + lane];
        int c0 = it * 128 + lane * 4;
        int my = (v.x != 0.f) + (v.y != 0.f) + (v.z != 0.f) + (v.w != 0.f);
        int inc = my;
        #pragma unroll
        for (int d = 1; d < 32; d <<= 1) {
            int t = __shfl_up_sync(0xffffffffu, inc, d);
            if (lane >= d) inc += t;
        }
        int total = __shfl_sync(0xffffffffu, inc, 31);
        int pos = count + inc - my;
        if (v.x != 0.f) { if (pos < MAXN) { my_idx[pos] = c0;     my_val[pos] = v.x; } pos++; }
        if (v.y != 0.f) { if (pos < MAXN) { my_idx[pos] = c0 + 1; my_val[pos] = v.y; } pos++; }
        if (v.z != 0.f) { if (pos < MAXN) { my_idx[pos] = c0 + 2; my_val[pos] = v.z; } pos++; }
        if (v.w != 0.f) { if (pos < MAXN) { my_idx[pos] = c0 + 3; my_val[pos] = v.w; } pos++; }
        count += total;
    }
    if (lane == 0) ncnt[warp] = count > MAXN ? MAXN : count;
}

// ---------------- weight / feature conversion ----------------
__global__ __launch_bounds__(256) void convert_weights(const float* __restrict__ W1,
                                                       const float* __restrict__ W_mid,
                                                       __nv_bfloat16* __restrict__ whi,
                                                       __nv_bfloat16* __restrict__ wlo)
{
    int idx = blockIdx.x * blockDim.x + threadIdx.x;
    if (idx >= WT_TOTAL) return;
    float w;
    if (idx < 192 * 256) {
        int n = idx / 256, k = idx % 256;
        w = W1[k * 192 + n];
    } else {
        int rel = idx - 192 * 256;
        int i = rel / (192 * 192);
        int r = rel % (192 * 192);
        int n = r / 192, k = r % 192;
        w = W_mid[(size_t)i * 192 * 192 + k * 192 + n];
    }
    __nv_bfloat16 h = __float2bfloat16(w);
    whi[idx] = h;
    wlo[idx] = __float2bfloat16(w - __bfloat162float(h));
}

__global__ __launch_bounds__(256) void convert_features(const float* __restrict__ f,
                                                        __nv_bfloat16* __restrict__ xhi,
                                                        __nv_bfloat16* __restrict__ xlo)
{
    int idx = blockIdx.x * blockDim.x + threadIdx.x;
    if (idx >= NN * INF) return;
    float v = f[idx];
    __nv_bfloat16 h = __float2bfloat16(v);
    xhi[idx] = h;
    xlo[idx] = __float2bfloat16(v - __bfloat162float(h));
}

// ---------------- split-bf16 HMMA GEMM: S[8192,192] = X[8192,K] @ Wt^T ----
// Wt stored [192 n][K k] rows (col-major B for mma .row.col).
// Tiles: BM=128, BN=96, BK=32. 256 thr / 8 warps (4x2), warp 32x48.
#define BM 128
#define BN 96
#define BK 32
#define ASTR 80            // padded row stride (bytes) for 32 bf16 = 64B + 16B pad
#define SA_H 0
#define SA_L (BM * ASTR)               // 10240
#define SB_H (2 * BM * ASTR)           // 20480
#define SB_L (2 * BM * ASTR + BN * ASTR)  // 28160
#define STAGE_BYTES (2 * BM * ASTR + 2 * BN * ASTR)   // 35840
#define GEMM_SMEM (2 * STAGE_BYTES)    // 71680

__global__ void __launch_bounds__(256, 2)
gemm_mma(const __nv_bfloat16* __restrict__ Xh, const __nv_bfloat16* __restrict__ Xl,
         const __nv_bfloat16* __restrict__ Wh, const __nv_bfloat16* __restrict__ Wl,
         float* __restrict__ S, int K)
{
    extern __shared__ char smem[];
    uint32_t sb = smem_u32(smem);
    int tid = threadIdx.x;
    int m0 = blockIdx.x * BM;
    int n0 = blockIdx.y * BN;
    int w = tid >> 5, lane = tid & 31;
    int wm = (w & 3) * 32;
    int wn = (w >> 2) * 48;

    float acc[2][6][4];
    #pragma unroll
    for (int mt = 0; mt < 2; mt++)
        #pragma unroll
        for (int nt = 0; nt < 6; nt++)
            #pragma unroll
            for (int q = 0; q < 4; q++) acc[mt][nt][q] = 0.f;

    int nch = K / BK;

    auto issue_load = [&](int c, int stg) {
        uint32_t base = sb + stg * STAGE_BYTES;
        int k0 = c * BK;
        // A: 128 rows x 4 segs of 16B, hi + lo
        #pragma unroll
        for (int r = 0; r < 2; r++) {
            int v = tid + r * 256;
            int row = v >> 2, seg = v & 3;
            size_t goff = (size_t)(m0 + row) * K + k0 + seg * 8;
            cp16(base + SA_H + row * ASTR + seg * 16, Xh + goff);
            cp16(base + SA_L + row * ASTR + seg * 16, Xl + goff);
        }
        // B: 96 rows x 4 segs, hi + lo
        {
            int row = tid >> 2, seg = tid & 3;   // rows 0..63
            size_t goff = (size_t)(n0 + row) * K + k0 + seg * 8;
            cp16(base + SB_H + row * ASTR + seg * 16, Wh + goff);
            cp16(base + SB_L + row * ASTR + seg * 16, Wl + goff);
        }
        if (tid < 128) {
            int v = tid + 256;
            int row = v >> 2, seg = v & 3;       // rows 64..95
            size_t goff = (size_t)(n0 + row) * K + k0 + seg * 8;
            cp16(base + SB_H + row * ASTR + seg * 16, Wh + goff);
            cp16(base + SB_L + row * ASTR + seg * 16, Wl + goff);
        }
    };

    auto compute = [&](int stg) {
        uint32_t base = sb + stg * STAGE_BYTES;
        #pragma unroll
        for (int ks = 0; ks < 2; ks++) {
            uint32_t ah[2][4], al[2][4], bhf[3][4], blf[3][4];
            #pragma unroll
            for (int mt = 0; mt < 2; mt++) {
                uint32_t arow = wm + mt * 16 + (lane & 15);
                uint32_t aoff = base + arow * ASTR + ks * 32 + (lane >> 4) * 16;
                ldmx4(ah[mt], aoff + SA_H);
                ldmx4(al[mt], aoff + SA_L);
            }
            #pragma unroll
            for (int p = 0; p < 3; p++) {
                uint32_t brow = wn + p * 16 + (lane & 7) + ((lane >> 4) << 3);
                uint32_t boff = base + brow * ASTR + ks * 32 + (((lane >> 3) & 1) * 16);
                ldmx4(bhf[p], boff + SB_H);
                ldmx4(blf[p], boff + SB_L);
            }
            #pragma unroll
            for (int mt = 0; mt < 2; mt++)
                #pragma unroll
                for (int nt = 0; nt < 6; nt++) {
                    const uint32_t* b2h = &bhf[nt >> 1][(nt & 1) * 2];
                    const uint32_t* b2l = &blf[nt >> 1][(nt & 1) * 2];
                    mma16816(acc[mt][nt], ah[mt], b2h);
                    mma16816(acc[mt][nt], ah[mt], b2l);
                    mma16816(acc[mt][nt], al[mt], b2h);
                }
        }
    };

    issue_load(0, 0);
    cp_commit();
    for (int c = 0; c < nch; c++) {
        if (c + 1 < nch) {
            issue_load(c + 1, (c + 1) & 1);
            cp_commit();
            cp_wait<1>();
        } else {
            cp_wait<0>();
        }
        __syncthreads();
        compute(c & 1);
        __syncthreads();
    }

    // epilogue: acc frag m16n8 -> S
    int rb = m0 + wm + (lane >> 2);
    int cb = n0 + wn + (lane & 3) * 2;
    #pragma unroll
    for (int mt = 0; mt < 2; mt++) {
        int r = rb + mt * 16;
        #pragma unroll
        for (int nt = 0; nt < 6; nt++) {
            int cc = cb + nt * 8;
            *reinterpret_cast<float2*>(&S[(size_t)r * HID + cc]) =
                make_float2(acc[mt][nt][0], acc[mt][nt][1]);
            *reinterpret_cast<float2*>(&S[(size_t)(r + 8) * HID + cc]) =
                make_float2(acc[mt][nt][2], acc[mt][nt][3]);
        }
    }
}

// ---------------- tiny GEMM for W_out (192x3) ----------------
__global__ __launch_bounds__(256) void gemm3_kernel(const float* __restrict__ X,
                                                    const float* __restrict__ W,
                                                    float* __restrict__ S)
{
    int r = blockIdx.x * blockDim.x + threadIdx.x;
    if (r >= NN) return;
    const float* x = X + (size_t)r * HID;
    float a0 = 0.f, a1 = 0.f, a2 = 0.f;
    #pragma unroll 4
    for (int k = 0; k < HID; k++) {
        float xv = x[k];
        a0 = fmaf(xv, W[k * 3 + 0], a0);
        a1 = fmaf(xv, W[k * 3 + 1], a1);
        a2 = fmaf(xv, W[k * 3 + 2], a2);
    }
    S[r * 3 + 0] = a0; S[r * 3 + 1] = a1; S[r * 3 + 2] = a2;
}

// ---------------- fused aggregation + bias + relu + residual + bf16-split ----
__global__ __launch_bounds__(256) void agg_kernel(const float* __restrict__ S,
                                                  const float* __restrict__ bias,
                                                  const float* __restrict__ res, int res_stride,
                                                  float* __restrict__ out,
                                                  float* __restrict__ out2,
                                                  __nv_bfloat16* __restrict__ ohi,
                                                  __nv_bfloat16* __restrict__ olo,
                                                  const int* __restrict__ nidx,
                                                  const float* __restrict__ nval,
                                                  const int* __restrict__ ncnt,
                                                  int n_out, int side, int do_relu)
{
    int warp = (blockIdx.x * blockDim.x + threadIdx.x) >> 5;
    int lane = threadIdx.x & 31;
    if (warp >= NN) return;
    int cnt = ncnt[warp];
    const int* ni = nidx + (size_t)warp * MAXN;
    const float* nv = nval + (size_t)warp * MAXN;
    float acc0 = 0.f, acc1 = 0.f;
    if (side > 32) {
        for (int i = 0; i < cnt; i++) {
            const float* sr = S + (size_t)ni[i] * n_out;
            float v = nv[i];
            acc0 = fmaf(v, sr[lane], acc0);
            acc1 = fmaf(v, sr[lane + 32], acc1);
        }
    } else {
        for (int i = 0; i < cnt; i++) {
            if (lane < side) acc0 = fmaf(nv[i], S[(size_t)ni[i] * n_out + lane], acc0);
        }
    }
    int nj = (n_out + 31) >> 5;
    for (int j = 0; j < nj; j++) {
        int c = 32 * j + lane;
        if (c < n_out) {
            float t = (c < side) ? (j == 0 ? acc0 : acc1)
                                 : S[(size_t)warp * n_out + c];
            t += bias[c];
            if (do_relu) t = fmaxf(t, 0.f);
            if (res) t = (res[(size_t)warp * res_stride + c] + t) * 0.5f;
            size_t idx = (size_t)warp * n_out + c;
            out[idx] = t;
            if (out2) out2[idx] = t;
            if (ohi) {
                __nv_bfloat16 h = __float2bfloat16(t);
                ohi[idx] = h;
                olo[idx] = __float2bfloat16(t - __bfloat162float(h));
            }
        }
    }
}

extern "C" void kernel_launch(void* const* d_in, const int* in_sizes, int n_in,
                              void* d_out, int out_size)
{
    const float* features = (const float*)d_in[0];
    const float* adj      = (const float*)d_in[1];
    const float* W1       = (const float*)d_in[2];
    const float* b1       = (const float*)d_in[3];
    const float* W_mid    = (const float*)d_in[4];
    const float* b_mid    = (const float*)d_in[5];
    const float* W_out    = (const float*)d_in[6];
    const float* b_out    = (const float*)d_in[7];
    float* out = (float*)d_out;
    float* coords   = out;
    float* feat_out = out + NN * 3;

    float *sup, *fb, *xb, *nval;
    __nv_bfloat16 *xhi, *xlo, *whi, *wlo;
    int *nidx, *ncnt;
    cudaGetSymbolAddress((void**)&sup,  g_support);
    cudaGetSymbolAddress((void**)&fb,   g_featbuf);
    cudaGetSymbolAddress((void**)&xb,   g_xbuf);
    cudaGetSymbolAddress((void**)&xhi,  g_xhi);
    cudaGetSymbolAddress((void**)&xlo,  g_xlo);
    cudaGetSymbolAddress((void**)&whi,  g_wthi);
    cudaGetSymbolAddress((void**)&wlo,  g_wtlo);
    cudaGetSymbolAddress((void**)&nidx, g_nidx);
    cudaGetSymbolAddress((void**)&nval, g_nval);
    cudaGetSymbolAddress((void**)&ncnt, g_ncnt);

    cudaFuncSetAttribute(gemm_mma, cudaFuncAttributeMaxDynamicSharedMemorySize, GEMM_SMEM);

    convert_weights<<<(WT_TOTAL + 255) / 256, 256>>>(W1, W_mid, whi, wlo);
    convert_features<<<(NN * INF + 255) / 256, 256>>>(features, xhi, xlo);
    build_csr<<<NN / 8, 256>>>(adj, nidx, nval, ncnt);

    dim3 ggrid(NN / BM, HID / BN);   // 64 x 2
    auto woff = [](int i) { return (size_t)192 * 256 + (size_t)i * 192 * 192; };

    // gc1 (K = 256)
    gemm_mma<<<ggrid, 256, GEMM_SMEM>>>(xhi, xlo, whi, wlo, sup, INF);
    agg_kernel<<<NN / 8, 256>>>(sup, b1, nullptr, 0, xb, nullptr, xhi, xlo,
                                nidx, nval, ncnt, HID, 64, 1);
    // gc2 + residual vs features[:, :192]
    gemm_mma<<<ggrid, 256, GEMM_SMEM>>>(xhi, xlo, whi + woff(0), wlo + woff(0), sup, HID);
    agg_kernel<<<NN / 8, 256>>>(sup, b_mid + 0, features, INF, fb, nullptr, xhi, xlo,
                                nidx, nval, ncnt, HID, 64, 1);

    const int pair_idx[5] = {1, 3, 5, 7, 9};
    for (int p = 0; p < 5; p++) {
        int i = pair_idx[p];
        gemm_mma<<<ggrid, 256, GEMM_SMEM>>>(xhi, xlo, whi + woff(i), wlo + woff(i), sup, HID);
        agg_kernel<<<NN / 8, 256>>>(sup, b_mid + (size_t)i * HID, nullptr, 0, xb, nullptr, xhi, xlo,
                                    nidx, nval, ncnt, HID, 64, 1);
        gemm_mma<<<ggrid, 256, GEMM_SMEM>>>(xhi, xlo, whi + woff(i + 1), wlo + woff(i + 1), sup, HID);
        agg_kernel<<<NN / 8, 256>>>(sup, b_mid + (size_t)(i + 1) * HID, fb, HID, fb, nullptr, xhi, xlo,
                                    nidx, nval, ncnt, HID, 64, 1);
    }

    // gc13 (+ residual); writes feat to output region too
    gemm_mma<<<ggrid, 256, GEMM_SMEM>>>(xhi, xlo, whi + woff(11), wlo + woff(11), sup, HID);
    agg_kernel<<<NN / 8, 256>>>(sup, b_mid + (size_t)11 * HID, fb, HID, fb, feat_out, nullptr, nullptr,
                                nidx, nval, ncnt, HID, 64, 1);

    // gc14: coords, side_len = 2, no relu
    gemm3_kernel<<<NN / 256, 256>>>(fb, W_out, sup);
    agg_kernel<<<NN / 8, 256>>>(sup, b_out, nullptr, 0, coords, nullptr, nullptr, nullptr,
                                nidx, nval, ncnt, 3, 2, 0);
}